// round 8
// baseline (speedup 1.0000x reference)
#include <cuda_runtime.h>
#include <math.h>

#define BB 2
#define LL 2048
#define DM 1024
#define NH 16
#define DK 64
#define BH (BB*NH)

typedef unsigned long long ull;

// ---------------- packed f32x2 helpers (FFMA2 path) ----------------
__device__ __forceinline__ ull pk2(float x, float y) {
    ull r; asm("mov.b64 %0,{%1,%2};" : "=l"(r) : "f"(x), "f"(y)); return r;
}
__device__ __forceinline__ ull dup2(float x) { return pk2(x, x); }
__device__ __forceinline__ void fma2(ull& d, ull a, ull b) {
    asm("fma.rn.f32x2 %0,%1,%2,%0;" : "+l"(d) : "l"(a), "l"(b));
}
__device__ __forceinline__ float2 up2(ull v) {
    float2 r; asm("mov.b64 {%0,%1},%2;" : "=f"(r.x), "=f"(r.y) : "l"(v)); return r;
}

// ---------------- tf32 legacy MMA helpers ----------------
__device__ __forceinline__ unsigned f2tf(float f) {
    unsigned u; asm("cvt.rna.tf32.f32 %0, %1;" : "=r"(u) : "f"(f)); return u;
}
__device__ __forceinline__ void mma8(float* c, const unsigned* a, const unsigned* b) {
    asm volatile("mma.sync.aligned.m16n8k8.row.col.f32.tf32.tf32.f32 "
        "{%0,%1,%2,%3}, {%4,%5,%6,%7}, {%8,%9}, {%0,%1,%2,%3};"
        : "+f"(c[0]), "+f"(c[1]), "+f"(c[2]), "+f"(c[3])
        : "r"(a[0]), "r"(a[1]), "r"(a[2]), "r"(a[3]), "r"(b[0]), "r"(b[1]));
}

// ---------------- scratch ----------------
__device__ float g_Q[(size_t)BB*NH*LL*DK];
__device__ float g_K[(size_t)BB*NH*LL*DK];
__device__ float g_V[(size_t)BB*NH*LL*DK];
__device__ float g_C[(size_t)BB*LL*DM];
__device__ float g_P[(size_t)BB*NH*LL*LL];
__device__ float g_m[(size_t)BB*NH*LL];
__device__ float g_s[(size_t)BB*NH*LL];
__device__ float g_c[(size_t)BB*NH*LL];
__device__ float g_rb[(size_t)BB*LL];

// ---------------- rel-bias precompute ----------------
__global__ void rb_kernel(const float* __restrict__ delta)
{
    int i = blockIdx.x * 256 + threadIdx.x;
    if (i < BB*LL) g_rb[i] = logf(delta[i] + 1e-6f);
}

// =====================================================================
// QKV projection (FFMA2, 128x128 tile, 8x8/thread)
// =====================================================================
__global__ __launch_bounds__(256) void qkv_gemm(
    const float* __restrict__ x, const float* __restrict__ delta,
    const float* __restrict__ Wq, const float* __restrict__ bq,
    const float* __restrict__ Wk, const float* __restrict__ bk,
    const float* __restrict__ Wv, const float* __restrict__ bv)
{
    const int which = blockIdx.z;
    const float* W    = (which == 0) ? Wq : (which == 1) ? Wk : Wv;
    const float* bias = (which == 0) ? bq : (which == 1) ? bk : bv;
    float* O          = (which == 0) ? g_Q : (which == 1) ? g_K : g_V;

    const int m0 = blockIdx.y * 128;
    const int n0 = blockIdx.x * 128;
    __shared__ float As[16][132];
    __shared__ float Bs[16][132];

    const int tid = threadIdx.x;
    const int tx = tid & 15, ty = tid >> 4;

    const int arow = tid >> 1, acol = (tid & 1) * 8;
    const int brow = tid >> 4, bcol = (tid & 15) * 8;
    const float ascale = (which == 2) ? delta[m0 + arow] : 1.0f;

    ull accp[8][4] = {};

    for (int kk = 0; kk < DM; kk += 16) {
        if (kk) __syncthreads();
        {
            const float* ap = &x[(size_t)(m0 + arow) * DM + kk + acol];
            float4 a0 = *(const float4*)(ap);
            float4 a1 = *(const float4*)(ap + 4);
            As[acol + 0][arow] = a0.x * ascale; As[acol + 1][arow] = a0.y * ascale;
            As[acol + 2][arow] = a0.z * ascale; As[acol + 3][arow] = a0.w * ascale;
            As[acol + 4][arow] = a1.x * ascale; As[acol + 5][arow] = a1.y * ascale;
            As[acol + 6][arow] = a1.z * ascale; As[acol + 7][arow] = a1.w * ascale;
        }
        {
            const float* bp = &W[(size_t)(kk + brow) * DM + n0 + bcol];
            *(float4*)&Bs[brow][bcol]     = *(const float4*)(bp);
            *(float4*)&Bs[brow][bcol + 4] = *(const float4*)(bp + 4);
        }
        __syncthreads();
        #pragma unroll
        for (int k = 0; k < 16; k++) {
            float4 a0 = *(const float4*)&As[k][ty * 4];
            float4 a1 = *(const float4*)&As[k][64 + ty * 4];
            longlong2 bq0 = *(const longlong2*)&Bs[k][tx * 4];
            longlong2 bq1 = *(const longlong2*)&Bs[k][64 + tx * 4];
            ull bb[4] = {(ull)bq0.x, (ull)bq0.y, (ull)bq1.x, (ull)bq1.y};
            ull ad[8] = {dup2(a0.x), dup2(a0.y), dup2(a0.z), dup2(a0.w),
                         dup2(a1.x), dup2(a1.y), dup2(a1.z), dup2(a1.w)};
            #pragma unroll
            for (int i = 0; i < 8; i++)
                #pragma unroll
                for (int jp = 0; jp < 4; jp++)
                    fma2(accp[i][jp], ad[i], bb[jp]);
        }
    }

    #pragma unroll
    for (int i = 0; i < 8; i++) {
        int gm = m0 + (i >> 2) * 64 + ty * 4 + (i & 3);
        int b = gm >> 11, l = gm & (LL - 1);
        #pragma unroll
        for (int gj = 0; gj < 2; gj++) {
            int gn = n0 + gj * 64 + tx * 4;
            int h = gn >> 6, d = gn & 63;
            float2 p0 = up2(accp[i][gj * 2 + 0]);
            float2 p1 = up2(accp[i][gj * 2 + 1]);
            float4 v = make_float4(p0.x + bias[gn+0], p0.y + bias[gn+1],
                                   p1.x + bias[gn+2], p1.y + bias[gn+3]);
            *(float4*)&O[(((size_t)(b * NH + h)) * LL + l) * DK + d] = v;
        }
    }
}

// =====================================================================
// Scores: tf32 MMA, 128q x all 2048k per block, online softmax stats
// =====================================================================
__global__ __launch_bounds__(256) void scores_kernel()
{
    extern __shared__ unsigned sm_u[];
    unsigned* Qs = sm_u;              // 8192 u
    unsigned* Ks = Qs + 8192;         // 8192 u
    float* rbs = (float*)(Ks + 8192); // 128
    float* smM = rbs + 128;           // 512
    float* smS = smM + 512;           // 512

    const int bh = blockIdx.y, b = bh >> 4;
    const int q0 = blockIdx.x * 128;
    const int tid = threadIdx.x, lane = tid & 31, warp = tid >> 5;
    const int wm = warp >> 2, wn = warp & 3;
    const int g = lane >> 2, t = lane & 3;

    {   // Q tile 128x64 -> A-frag layout (loaded once)
        int m = tid >> 1;
        const float* qp = &g_Q[(((size_t)bh) * LL + q0 + m) * DK];
        int mf = m >> 4, gg = m & 7, hm = (m >> 3) & 1;
        #pragma unroll
        for (int it = 0; it < 8; it++) {
            int k0 = (tid & 1) * 32 + it * 4;
            float4 v = *(const float4*)(qp + k0);
            int k8 = k0 >> 3, hk = (k0 >> 2) & 1, r = hm + 2 * hk;
            int base = ((mf * 8 + k8) * 32 + gg * 4) * 4 + r;
            Qs[base] = f2tf(v.x); Qs[base+4] = f2tf(v.y);
            Qs[base+8] = f2tf(v.z); Qs[base+12] = f2tf(v.w);
        }
    }

    float mr[4][2], sr[4][2];
    #pragma unroll
    for (int i = 0; i < 4; i++) { mr[i][0] = mr[i][1] = -1e30f; sr[i][0] = sr[i][1] = 0.0f; }

    for (int kt = 0; kt < LL / 128; kt++) {
        __syncthreads();
        {   // K tile 128x64 -> B-frag layout
            int n = tid >> 1;
            const float* kp = &g_K[(((size_t)bh) * LL + kt * 128 + n) * DK];
            int nf = n >> 3, gg = n & 7;
            #pragma unroll
            for (int it = 0; it < 8; it++) {
                int k0 = (tid & 1) * 32 + it * 4;
                float4 v = *(const float4*)(kp + k0);
                int k8 = k0 >> 3, r = (k0 >> 2) & 1;
                int base = ((nf * 8 + k8) * 32 + gg * 4) * 2 + r;
                Ks[base] = f2tf(v.x); Ks[base+2] = f2tf(v.y);
                Ks[base+4] = f2tf(v.z); Ks[base+6] = f2tf(v.w);
            }
            if (tid < 128) rbs[tid] = g_rb[(size_t)b * LL + kt * 128 + tid];
        }
        __syncthreads();

        float c[4][4][4] = {};
        #pragma unroll
        for (int k8 = 0; k8 < 8; k8++) {
            unsigned a[4][4], bf[4][2];
            #pragma unroll
            for (int i = 0; i < 4; i++) {
                int base = (((wm * 4 + i) * 8 + k8) * 32 + lane) * 4;
                *(uint4*)a[i] = *(const uint4*)&Qs[base];
            }
            #pragma unroll
            for (int j = 0; j < 4; j++) {
                int base = (((wn * 4 + j) * 8 + k8) * 32 + lane) * 2;
                *(uint2*)bf[j] = *(const uint2*)&Ks[base];
            }
            #pragma unroll
            for (int i = 0; i < 4; i++)
                #pragma unroll
                for (int j = 0; j < 4; j++)
                    mma8(c[i][j], a[i], bf[j]);
        }

        // bias + P store + online stats
        #pragma unroll
        for (int i = 0; i < 4; i++) {
            int row0 = q0 + wm * 64 + i * 16 + g;
            #pragma unroll
            for (int half = 0; half < 2; half++) {
                int row = row0 + half * 8;
                float qrf = (float)row;
                float sv[4][2];
                float vmax = -1e30f;
                #pragma unroll
                for (int j = 0; j < 4; j++) {
                    int lcol = wn * 32 + j * 8 + t * 2;
                    int kg = kt * 128 + lcol;
                    float v0 = c[i][j][half*2+0] * 0.125f - 0.1f * fabsf(qrf - (float)kg)     + rbs[lcol];
                    float v1 = c[i][j][half*2+1] * 0.125f - 0.1f * fabsf(qrf - (float)(kg+1)) + rbs[lcol+1];
                    sv[j][0] = v0; sv[j][1] = v1;
                    vmax = fmaxf(vmax, fmaxf(v0, v1));
                    __stcs((float2*)&g_P[(((size_t)bh) * LL + row) * LL + kg],
                           make_float2(v0, v1));
                }
                vmax = fmaxf(vmax, __shfl_xor_sync(0xffffffffu, vmax, 1));
                vmax = fmaxf(vmax, __shfl_xor_sync(0xffffffffu, vmax, 2));
                float newm = fmaxf(mr[i][half], vmax);
                float se = 0.0f;
                #pragma unroll
                for (int j = 0; j < 4; j++)
                    se += __expf(sv[j][0] - newm) + __expf(sv[j][1] - newm);
                se += __shfl_xor_sync(0xffffffffu, se, 1);
                se += __shfl_xor_sync(0xffffffffu, se, 2);
                sr[i][half] = sr[i][half] * __expf(mr[i][half] - newm) + se;
                mr[i][half] = newm;
            }
        }
    }

    __syncthreads();
    if (t == 0) {
        #pragma unroll
        for (int i = 0; i < 4; i++)
            #pragma unroll
            for (int half = 0; half < 2; half++) {
                int row = wm * 64 + i * 16 + half * 8 + g;
                smM[wn * 128 + row] = mr[i][half];
                smS[wn * 128 + row] = sr[i][half];
            }
    }
    __syncthreads();
    if (tid < 128) {
        float M = smM[tid];
        #pragma unroll
        for (int w = 1; w < 4; w++) M = fmaxf(M, smM[w * 128 + tid]);
        float S = 0.0f;
        #pragma unroll
        for (int w = 0; w < 4; w++) S += smS[w * 128 + tid] * __expf(smM[w * 128 + tid] - M);
        size_t ridx = (size_t)bh * LL + q0 + tid;
        g_m[ridx] = M;
        g_s[ridx] = S;
        g_c[ridx] = M + __logf(S);
    }
}

// =====================================================================
// Context: softmax(P) @ V, tf32 MMA; 128q x 64d, K-chunks of 64 keys
// =====================================================================
__global__ __launch_bounds__(256) void context_kernel()
{
    extern __shared__ unsigned sm_u[];
    unsigned* Ps = sm_u;           // 8192 u
    unsigned* Vs = Ps + 8192;      // 4096 u
    float* mrow = (float*)(Vs + 4096);
    float* irow = mrow + 128;

    const int bh = blockIdx.y, b = bh >> 4, hh = bh & 15;
    const int q0 = blockIdx.x * 128;
    const int tid = threadIdx.x, lane = tid & 31, warp = tid >> 5;
    const int wm = warp >> 1, wn = warp & 1;
    const int g = lane >> 2, t = lane & 3;

    if (tid < 128) {
        size_t r = (size_t)bh * LL + q0 + tid;
        mrow[tid] = g_m[r];
        irow[tid] = 1.0f / g_s[r];
    }
    __syncthreads();

    const int pm = tid >> 1;
    const float pmax = mrow[pm];
    const float* Pbase = &g_P[(((size_t)bh) * LL + q0 + pm) * LL];
    const int vk = tid >> 2;

    float c[2][4][4] = {};

    for (int kc = 0; kc < LL; kc += 64) {
        if (kc) __syncthreads();
        {   // P chunk 128x64: exp + tf32 -> A-frag layout
            int mf = pm >> 4, gg = pm & 7, hm = (pm >> 3) & 1;
            #pragma unroll
            for (int it = 0; it < 8; it++) {
                int k0 = (tid & 1) * 32 + it * 4;
                float4 v = __ldcs((const float4*)(Pbase + kc + k0));
                int k8 = k0 >> 3, hk = (k0 >> 2) & 1, r = hm + 2 * hk;
                int base = ((mf * 8 + k8) * 32 + gg * 4) * 4 + r;
                Ps[base]    = f2tf(__expf(v.x - pmax));
                Ps[base+4]  = f2tf(__expf(v.y - pmax));
                Ps[base+8]  = f2tf(__expf(v.z - pmax));
                Ps[base+12] = f2tf(__expf(v.w - pmax));
            }
        }
        {   // V chunk 64x64 -> B-frag layout
            const float* vp = &g_V[(((size_t)bh) * LL + kc + vk) * DK];
            int tig = vk & 3, k8 = vk >> 3, r = (vk >> 2) & 1;
            #pragma unroll
            for (int it = 0; it < 4; it++) {
                int ne = (tid & 3) * 16 + it * 4;
                float4 v = *(const float4*)(vp + ne);
                int nf = ne >> 3, g0 = ne & 7;
                int base = ((nf * 8 + k8) * 32 + g0 * 4 + tig) * 2 + r;
                Vs[base] = f2tf(v.x); Vs[base+8] = f2tf(v.y);
                Vs[base+16] = f2tf(v.z); Vs[base+24] = f2tf(v.w);
            }
        }
        __syncthreads();
        #pragma unroll
        for (int k8 = 0; k8 < 8; k8++) {
            unsigned a[2][4], bf[4][2];
            #pragma unroll
            for (int i = 0; i < 2; i++) {
                int base = (((wm * 2 + i) * 8 + k8) * 32 + lane) * 4;
                *(uint4*)a[i] = *(const uint4*)&Ps[base];
            }
            #pragma unroll
            for (int j = 0; j < 4; j++) {
                int base = (((wn * 4 + j) * 8 + k8) * 32 + lane) * 2;
                *(uint2*)bf[j] = *(const uint2*)&Vs[base];
            }
            #pragma unroll
            for (int i = 0; i < 2; i++)
                #pragma unroll
                for (int j = 0; j < 4; j++)
                    mma8(c[i][j], a[i], bf[j]);
        }
    }

    #pragma unroll
    for (int i = 0; i < 2; i++) {
        int lq0 = wm * 32 + i * 16 + g;
        #pragma unroll
        for (int j = 0; j < 4; j++) {
            int d = wn * 32 + j * 8 + t * 2;
            {
                float sc = irow[lq0];
                int q = q0 + lq0;
                *(float2*)&g_C[((size_t)(b * LL + q)) * DM + hh * 64 + d] =
                    make_float2(c[i][j][0] * sc, c[i][j][1] * sc);
            }
            {
                float sc = irow[lq0 + 8];
                int q = q0 + lq0 + 8;
                *(float2*)&g_C[((size_t)(b * LL + q)) * DM + hh * 64 + d] =
                    make_float2(c[i][j][2] * sc, c[i][j][3] * sc);
            }
        }
    }
}

// =====================================================================
// Head-mean of attention
// =====================================================================
__global__ void mean_kernel(float* __restrict__ outmean)
{
    size_t idx4 = (size_t)blockIdx.x * 256 + threadIdx.x;
    int k4 = (int)(idx4 & (LL / 4 - 1)) * 4;
    size_t bq = idx4 / (LL / 4);
    int q = (int)(bq & (LL - 1));
    int b = (int)(bq >> 11);
    float ax = 0, ay = 0, az = 0, aw = 0;
    #pragma unroll
    for (int h = 0; h < NH; h++) {
        int bh = b * NH + h;
        float cc = g_c[(size_t)bh * LL + q];
        float4 v = __ldcs((const float4*)&g_P[((size_t)bh * LL + q) * LL + k4]);
        ax += __expf(v.x - cc); ay += __expf(v.y - cc);
        az += __expf(v.z - cc); aw += __expf(v.w - cc);
    }
    const float inv = 1.0f / NH;
    *(float4*)&outmean[bq * LL + k4] = make_float4(ax*inv, ay*inv, az*inv, aw*inv);
}

// =====================================================================
// Output projection (FFMA2, 128x128 tile, 8x8/thread)
// =====================================================================
__global__ __launch_bounds__(256) void out_gemm(const float* __restrict__ Wo,
                                                const float* __restrict__ bo,
                                                float* __restrict__ out)
{
    const int m0 = blockIdx.y * 128;
    const int n0 = blockIdx.x * 128;
    __shared__ float As[16][132];
    __shared__ float Bs[16][132];

    const int tid = threadIdx.x;
    const int tx = tid & 15, ty = tid >> 4;
    const int arow = tid >> 1, acol = (tid & 1) * 8;
    const int brow = tid >> 4, bcol = (tid & 15) * 8;

    ull accp[8][4] = {};

    for (int kk = 0; kk < DM; kk += 16) {
        if (kk) __syncthreads();
        {
            const float* ap = &g_C[(size_t)(m0 + arow) * DM + kk + acol];
            float4 a0 = *(const float4*)(ap);
            float4 a1 = *(const float4*)(ap + 4);
            As[acol + 0][arow] = a0.x; As[acol + 1][arow] = a0.y;
            As[acol + 2][arow] = a0.z; As[acol + 3][arow] = a0.w;
            As[acol + 4][arow] = a1.x; As[acol + 5][arow] = a1.y;
            As[acol + 6][arow] = a1.z; As[acol + 7][arow] = a1.w;
        }
        {
            const float* bp = &Wo[(size_t)(kk + brow) * DM + n0 + bcol];
            *(float4*)&Bs[brow][bcol]     = *(const float4*)(bp);
            *(float4*)&Bs[brow][bcol + 4] = *(const float4*)(bp + 4);
        }
        __syncthreads();
        #pragma unroll
        for (int k = 0; k < 16; k++) {
            float4 a0 = *(const float4*)&As[k][ty * 4];
            float4 a1 = *(const float4*)&As[k][64 + ty * 4];
            longlong2 bq0 = *(const longlong2*)&Bs[k][tx * 4];
            longlong2 bq1 = *(const longlong2*)&Bs[k][64 + tx * 4];
            ull bb[4] = {(ull)bq0.x, (ull)bq0.y, (ull)bq1.x, (ull)bq1.y};
            ull ad[8] = {dup2(a0.x), dup2(a0.y), dup2(a0.z), dup2(a0.w),
                         dup2(a1.x), dup2(a1.y), dup2(a1.z), dup2(a1.w)};
            #pragma unroll
            for (int i = 0; i < 8; i++)
                #pragma unroll
                for (int jp = 0; jp < 4; jp++)
                    fma2(accp[i][jp], ad[i], bb[jp]);
        }
    }

    #pragma unroll
    for (int i = 0; i < 8; i++) {
        int gm = m0 + (i >> 2) * 64 + ty * 4 + (i & 3);
        #pragma unroll
        for (int gj = 0; gj < 2; gj++) {
            int gn = n0 + gj * 64 + tx * 4;
            float2 p0 = up2(accp[i][gj * 2 + 0]);
            float2 p1 = up2(accp[i][gj * 2 + 1]);
            float4 v = make_float4(p0.x + bo[gn+0], p0.y + bo[gn+1],
                                   p1.x + bo[gn+2], p1.y + bo[gn+3]);
            *(float4*)&out[(size_t)gm * DM + gn] = v;
        }
    }
}

// ---------------- launch ----------------
extern "C" void kernel_launch(void* const* d_in, const int* in_sizes, int n_in,
                              void* d_out, int out_size)
{
    const float* x     = (const float*)d_in[0];
    const float* delta = (const float*)d_in[1];
    const float* Wq    = (const float*)d_in[2];
    const float* bq    = (const float*)d_in[3];
    const float* Wk    = (const float*)d_in[4];
    const float* bk    = (const float*)d_in[5];
    const float* Wv    = (const float*)d_in[6];
    const float* bv    = (const float*)d_in[7];
    const float* Wo    = (const float*)d_in[8];
    const float* bo    = (const float*)d_in[9];
    float* out = (float*)d_out;
    float* outmean = out + (size_t)BB * LL * DM;

    const int SC_SMEM  = 2 * 8192 * 4 + (128 + 1024) * 4;    // ~70 KB
    const int CTX_SMEM = (8192 + 4096) * 4 + 256 * 4;        // ~50 KB

    cudaFuncSetAttribute(scores_kernel, cudaFuncAttributeMaxDynamicSharedMemorySize, SC_SMEM);
    cudaFuncSetAttribute(context_kernel, cudaFuncAttributeMaxDynamicSharedMemorySize, CTX_SMEM);

    rb_kernel<<<(BB * LL + 255) / 256, 256>>>(delta);
    qkv_gemm<<<dim3(DM / 128, (BB * LL) / 128, 3), 256>>>(x, delta, Wq, bq, Wk, bk, Wv, bv);
    scores_kernel<<<dim3(LL / 128, BH), 256, SC_SMEM>>>();
    context_kernel<<<dim3(LL / 128, BH), 256, CTX_SMEM>>>();
    mean_kernel<<<(unsigned)((size_t)BB * LL * LL / 4 / 256), 256>>>(outmean);
    out_gemm<<<dim3(DM / 128, (BB * LL) / 128), 256>>>(Wo, bo, out);
}

// round 9
// speedup vs baseline: 1.1722x; 1.1722x over previous
#include <cuda_runtime.h>
#include <math.h>

#define BB 2
#define LL 2048
#define DM 1024
#define NH 16
#define DK 64
#define BH (BB*NH)

typedef unsigned long long ull;

// ---------------- packed f32x2 helpers (FFMA2 path) ----------------
__device__ __forceinline__ ull pk2(float x, float y) {
    ull r; asm("mov.b64 %0,{%1,%2};" : "=l"(r) : "f"(x), "f"(y)); return r;
}
__device__ __forceinline__ ull dup2(float x) { return pk2(x, x); }
__device__ __forceinline__ void fma2(ull& d, ull a, ull b) {
    asm("fma.rn.f32x2 %0,%1,%2,%0;" : "+l"(d) : "l"(a), "l"(b));
}
__device__ __forceinline__ float2 up2(ull v) {
    float2 r; asm("mov.b64 {%0,%1},%2;" : "=f"(r.x), "=f"(r.y) : "l"(v)); return r;
}

// ---------------- tf32 MMA helpers ----------------
__device__ __forceinline__ unsigned f2tf(float f) {
    unsigned u; asm("cvt.rna.tf32.f32 %0, %1;" : "=r"(u) : "f"(f)); return u;
}
__device__ __forceinline__ void mma8(float* c, const unsigned* a, const unsigned* b) {
    asm volatile("mma.sync.aligned.m16n8k8.row.col.f32.tf32.tf32.f32 "
        "{%0,%1,%2,%3}, {%4,%5,%6,%7}, {%8,%9}, {%0,%1,%2,%3};"
        : "+f"(c[0]), "+f"(c[1]), "+f"(c[2]), "+f"(c[3])
        : "r"(a[0]), "r"(a[1]), "r"(a[2]), "r"(a[3]), "r"(b[0]), "r"(b[1]));
}

// ---------------- scratch ----------------
__device__ float g_Q[(size_t)BB*NH*LL*DK];
__device__ float g_K[(size_t)BB*NH*LL*DK];
__device__ float g_V[(size_t)BB*NH*LL*DK];
__device__ float g_C[(size_t)BB*LL*DM];
__device__ float g_P[(size_t)BB*NH*LL*LL];
__device__ float g_m[(size_t)BB*NH*LL];
__device__ float g_s[(size_t)BB*NH*LL];
__device__ float g_c[(size_t)BB*NH*LL];
__device__ float g_rb[(size_t)BB*LL];

// ---------------- rel-bias precompute ----------------
__global__ void rb_kernel(const float* __restrict__ delta)
{
    int i = blockIdx.x * 256 + threadIdx.x;
    if (i < BB*LL) g_rb[i] = logf(delta[i] + 1e-6f);
}

// =====================================================================
// QKV projection (FFMA2, 128x128 tile, 8x8/thread)  [unchanged from R5]
// =====================================================================
__global__ __launch_bounds__(256) void qkv_gemm(
    const float* __restrict__ x, const float* __restrict__ delta,
    const float* __restrict__ Wq, const float* __restrict__ bq,
    const float* __restrict__ Wk, const float* __restrict__ bk,
    const float* __restrict__ Wv, const float* __restrict__ bv)
{
    const int which = blockIdx.z;
    const float* W    = (which == 0) ? Wq : (which == 1) ? Wk : Wv;
    const float* bias = (which == 0) ? bq : (which == 1) ? bk : bv;
    float* O          = (which == 0) ? g_Q : (which == 1) ? g_K : g_V;

    const int m0 = blockIdx.y * 128;
    const int n0 = blockIdx.x * 128;
    __shared__ float As[16][132];
    __shared__ float Bs[16][132];

    const int tid = threadIdx.x;
    const int tx = tid & 15, ty = tid >> 4;

    const int arow = tid >> 1, acol = (tid & 1) * 8;
    const int brow = tid >> 4, bcol = (tid & 15) * 8;
    const float ascale = (which == 2) ? delta[m0 + arow] : 1.0f;

    ull accp[8][4] = {};

    for (int kk = 0; kk < DM; kk += 16) {
        if (kk) __syncthreads();
        {
            const float* ap = &x[(size_t)(m0 + arow) * DM + kk + acol];
            float4 a0 = *(const float4*)(ap);
            float4 a1 = *(const float4*)(ap + 4);
            As[acol + 0][arow] = a0.x * ascale; As[acol + 1][arow] = a0.y * ascale;
            As[acol + 2][arow] = a0.z * ascale; As[acol + 3][arow] = a0.w * ascale;
            As[acol + 4][arow] = a1.x * ascale; As[acol + 5][arow] = a1.y * ascale;
            As[acol + 6][arow] = a1.z * ascale; As[acol + 7][arow] = a1.w * ascale;
        }
        {
            const float* bp = &W[(size_t)(kk + brow) * DM + n0 + bcol];
            *(float4*)&Bs[brow][bcol]     = *(const float4*)(bp);
            *(float4*)&Bs[brow][bcol + 4] = *(const float4*)(bp + 4);
        }
        __syncthreads();
        #pragma unroll
        for (int k = 0; k < 16; k++) {
            float4 a0 = *(const float4*)&As[k][ty * 4];
            float4 a1 = *(const float4*)&As[k][64 + ty * 4];
            longlong2 bq0 = *(const longlong2*)&Bs[k][tx * 4];
            longlong2 bq1 = *(const longlong2*)&Bs[k][64 + tx * 4];
            ull bb[4] = {(ull)bq0.x, (ull)bq0.y, (ull)bq1.x, (ull)bq1.y};
            ull ad[8] = {dup2(a0.x), dup2(a0.y), dup2(a0.z), dup2(a0.w),
                         dup2(a1.x), dup2(a1.y), dup2(a1.z), dup2(a1.w)};
            #pragma unroll
            for (int i = 0; i < 8; i++)
                #pragma unroll
                for (int jp = 0; jp < 4; jp++)
                    fma2(accp[i][jp], ad[i], bb[jp]);
        }
    }

    #pragma unroll
    for (int i = 0; i < 8; i++) {
        int gm = m0 + (i >> 2) * 64 + ty * 4 + (i & 3);
        int b = gm >> 11, l = gm & (LL - 1);
        #pragma unroll
        for (int gj = 0; gj < 2; gj++) {
            int gn = n0 + gj * 64 + tx * 4;
            int h = gn >> 6, d = gn & 63;
            float2 p0 = up2(accp[i][gj * 2 + 0]);
            float2 p1 = up2(accp[i][gj * 2 + 1]);
            float4 v = make_float4(p0.x + bias[gn+0], p0.y + bias[gn+1],
                                   p1.x + bias[gn+2], p1.y + bias[gn+3]);
            *(float4*)&O[(((size_t)(b * NH + h)) * LL + l) * DK + d] = v;
        }
    }
}

// =====================================================================
// Scores: tf32 MMA with k-permuted smem layout.
// kperm = (k&3)*16 + (k>>2), row stride 68. One LDS.128 per fragment pair.
// =====================================================================
__global__ __launch_bounds__(256) void scores_kernel()
{
    extern __shared__ unsigned sm_u[];
    unsigned* Qs = sm_u;                    // 128*68
    unsigned* Ks = Qs + 128*68;             // 128*68
    float* rbs = (float*)(Ks + 128*68);     // 128
    float* smM = rbs + 128;                 // 512
    float* smS = smM + 512;                 // 512

    const int bh = blockIdx.y, b = bh >> 4;
    const int q0 = blockIdx.x * 128;
    const int tid = threadIdx.x, lane = tid & 31, warp = tid >> 5;
    const int wm = warp >> 2, wn = warp & 3;
    const int g = lane >> 2, t = lane & 3;

    {   // Q tile 128x64 -> permuted layout (loaded once)
        const int m = tid >> 1, ch0 = (tid & 1) * 8;
        const float* qp = &g_Q[((size_t)bh * LL + q0 + m) * DK];
        unsigned* qrow = Qs + m * 68;
        #pragma unroll
        for (int cc = 0; cc < 8; cc++) {
            int c = ch0 + cc;
            float4 v = *(const float4*)(qp + c * 4);
            qrow[c]      = f2tf(v.x);
            qrow[16 + c] = f2tf(v.y);
            qrow[32 + c] = f2tf(v.z);
            qrow[48 + c] = f2tf(v.w);
        }
    }

    float mr[4][2], sr[4][2];
    #pragma unroll
    for (int i = 0; i < 4; i++) { mr[i][0] = mr[i][1] = -1e30f; sr[i][0] = sr[i][1] = 0.0f; }

    for (int kt = 0; kt < LL / 128; kt++) {
        __syncthreads();
        {   // K tile 128x64 -> permuted layout
            const int n = tid >> 1, ch0 = (tid & 1) * 8;
            const float* kp = &g_K[((size_t)bh * LL + kt * 128 + n) * DK];
            unsigned* krow = Ks + n * 68;
            #pragma unroll
            for (int cc = 0; cc < 8; cc++) {
                int c = ch0 + cc;
                float4 v = *(const float4*)(kp + c * 4);
                krow[c]      = f2tf(v.x);
                krow[16 + c] = f2tf(v.y);
                krow[32 + c] = f2tf(v.z);
                krow[48 + c] = f2tf(v.w);
            }
            if (tid < 128) rbs[tid] = g_rb[(size_t)b * LL + kt * 128 + tid];
        }
        __syncthreads();

        float c4[4][4][4] = {};
        #pragma unroll
        for (int jj = 0; jj < 4; jj++) {
            uint4 alo[4], ahi[4], bf[4];
            #pragma unroll
            for (int i = 0; i < 4; i++) {
                int row = wm * 64 + i * 16 + g;
                alo[i] = *(const uint4*)&Qs[row * 68 + t * 16 + 4 * jj];
                ahi[i] = *(const uint4*)&Qs[(row + 8) * 68 + t * 16 + 4 * jj];
            }
            #pragma unroll
            for (int jn = 0; jn < 4; jn++) {
                int n = wn * 32 + jn * 8 + g;
                bf[jn] = *(const uint4*)&Ks[n * 68 + t * 16 + 4 * jj];
            }
            #pragma unroll
            for (int i = 0; i < 4; i++) {
                unsigned aA[4] = {alo[i].x, ahi[i].x, alo[i].y, ahi[i].y};
                unsigned aB[4] = {alo[i].z, ahi[i].z, alo[i].w, ahi[i].w};
                #pragma unroll
                for (int jn = 0; jn < 4; jn++) {
                    unsigned b0[2] = {bf[jn].x, bf[jn].y};
                    unsigned b1[2] = {bf[jn].z, bf[jn].w};
                    mma8(c4[i][jn], aA, b0);
                    mma8(c4[i][jn], aB, b1);
                }
            }
        }

        // bias + P store + online stats (same as R8)
        #pragma unroll
        for (int i = 0; i < 4; i++) {
            int row0 = q0 + wm * 64 + i * 16 + g;
            #pragma unroll
            for (int half = 0; half < 2; half++) {
                int row = row0 + half * 8;
                float qrf = (float)row;
                float sv[4][2];
                float vmax = -1e30f;
                #pragma unroll
                for (int j = 0; j < 4; j++) {
                    int lcol = wn * 32 + j * 8 + t * 2;
                    int kg = kt * 128 + lcol;
                    float v0 = c4[i][j][half*2+0] * 0.125f - 0.1f * fabsf(qrf - (float)kg)     + rbs[lcol];
                    float v1 = c4[i][j][half*2+1] * 0.125f - 0.1f * fabsf(qrf - (float)(kg+1)) + rbs[lcol+1];
                    sv[j][0] = v0; sv[j][1] = v1;
                    vmax = fmaxf(vmax, fmaxf(v0, v1));
                    __stcs((float2*)&g_P[(((size_t)bh) * LL + row) * LL + kg],
                           make_float2(v0, v1));
                }
                vmax = fmaxf(vmax, __shfl_xor_sync(0xffffffffu, vmax, 1));
                vmax = fmaxf(vmax, __shfl_xor_sync(0xffffffffu, vmax, 2));
                float newm = fmaxf(mr[i][half], vmax);
                float se = 0.0f;
                #pragma unroll
                for (int j = 0; j < 4; j++)
                    se += __expf(sv[j][0] - newm) + __expf(sv[j][1] - newm);
                se += __shfl_xor_sync(0xffffffffu, se, 1);
                se += __shfl_xor_sync(0xffffffffu, se, 2);
                sr[i][half] = sr[i][half] * __expf(mr[i][half] - newm) + se;
                mr[i][half] = newm;
            }
        }
    }

    __syncthreads();
    if (t == 0) {
        #pragma unroll
        for (int i = 0; i < 4; i++)
            #pragma unroll
            for (int half = 0; half < 2; half++) {
                int row = wm * 64 + i * 16 + half * 8 + g;
                smM[wn * 128 + row] = mr[i][half];
                smS[wn * 128 + row] = sr[i][half];
            }
    }
    __syncthreads();
    if (tid < 128) {
        float M = smM[tid];
        #pragma unroll
        for (int w = 1; w < 4; w++) M = fmaxf(M, smM[w * 128 + tid]);
        float S = 0.0f;
        #pragma unroll
        for (int w = 0; w < 4; w++) S += smS[w * 128 + tid] * __expf(smM[w * 128 + tid] - M);
        size_t ridx = (size_t)bh * LL + q0 + tid;
        g_m[ridx] = M;
        g_s[ridx] = S;
        g_c[ridx] = M + __logf(S);
    }
}

// =====================================================================
// Context: softmax(P) @ V, tf32 MMA with k-permuted layout; 64-key chunks
// =====================================================================
__global__ __launch_bounds__(256) void context_kernel()
{
    extern __shared__ unsigned sm_u[];
    unsigned* Ps = sm_u;                  // 128*68
    unsigned* Vs = Ps + 128*68;           // 64*68
    float* mrow = (float*)(Vs + 64*68);   // 128
    float* irow = mrow + 128;             // 128

    const int bh = blockIdx.y, b = bh >> 4, hh = bh & 15;
    const int q0 = blockIdx.x * 128;
    const int tid = threadIdx.x, lane = tid & 31, warp = tid >> 5;
    const int wm = warp >> 1, wn = warp & 1;
    const int g = lane >> 2, t = lane & 3;

    if (tid < 128) {
        size_t r = (size_t)bh * LL + q0 + tid;
        mrow[tid] = g_m[r];
        irow[tid] = 1.0f / g_s[r];
    }
    __syncthreads();

    const int pm = tid >> 1, pch0 = (tid & 1) * 8;
    const float pmax = mrow[pm];
    const float* Pbase = &g_P[(((size_t)bh) * LL + q0 + pm) * LL];
    unsigned* prow_s = Ps + pm * 68;

    const int vd = tid & 63;              // output dim
    const int vseg = tid >> 6;            // 0..3: k segment of 16
    unsigned* vrow_s = Vs + vd * 68;

    float c4[2][4][4] = {};

    for (int kc = 0; kc < LL; kc += 64) {
        __syncthreads();
        // P chunk 128x64: exp + tf32 -> permuted layout
        #pragma unroll
        for (int cc = 0; cc < 8; cc++) {
            int c = pch0 + cc;
            float4 v = __ldcs((const float4*)(Pbase + kc + c * 4));
            prow_s[c]      = f2tf(__expf(v.x - pmax));
            prow_s[16 + c] = f2tf(__expf(v.y - pmax));
            prow_s[32 + c] = f2tf(__expf(v.z - pmax));
            prow_s[48 + c] = f2tf(__expf(v.w - pmax));
        }
        // V chunk 64x64 transposed gather -> [d][kperm] (coalesced LDG.32)
        {
            const float* vbase = &g_V[(((size_t)bh) * LL + kc) * DK + vd];
            #pragma unroll
            for (int r = 0; r < 4; r++) {
                unsigned tmp[4];
                #pragma unroll
                for (int i2 = 0; i2 < 4; i2++) {
                    int k = 16 * vseg + r + 4 * i2;
                    tmp[i2] = f2tf(vbase[(size_t)k * DK]);
                }
                *(uint4*)&vrow_s[r * 16 + 4 * vseg] = *(uint4*)tmp;
            }
        }
        __syncthreads();
        // MMA: warp tile 32q x 32d
        #pragma unroll
        for (int jj = 0; jj < 4; jj++) {
            uint4 alo[2], ahi[2], bf[4];
            #pragma unroll
            for (int i = 0; i < 2; i++) {
                int row = wm * 32 + i * 16 + g;
                alo[i] = *(const uint4*)&Ps[row * 68 + t * 16 + 4 * jj];
                ahi[i] = *(const uint4*)&Ps[(row + 8) * 68 + t * 16 + 4 * jj];
            }
            #pragma unroll
            for (int jn = 0; jn < 4; jn++) {
                int n = wn * 32 + jn * 8 + g;
                bf[jn] = *(const uint4*)&Vs[n * 68 + t * 16 + 4 * jj];
            }
            #pragma unroll
            for (int i = 0; i < 2; i++) {
                unsigned aA[4] = {alo[i].x, ahi[i].x, alo[i].y, ahi[i].y};
                unsigned aB[4] = {alo[i].z, ahi[i].z, alo[i].w, ahi[i].w};
                #pragma unroll
                for (int jn = 0; jn < 4; jn++) {
                    unsigned b0[2] = {bf[jn].x, bf[jn].y};
                    unsigned b1[2] = {bf[jn].z, bf[jn].w};
                    mma8(c4[i][jn], aA, b0);
                    mma8(c4[i][jn], aB, b1);
                }
            }
        }
    }

    #pragma unroll
    for (int i = 0; i < 2; i++) {
        int lq0 = wm * 32 + i * 16 + g;
        #pragma unroll
        for (int j = 0; j < 4; j++) {
            int d = wn * 32 + j * 8 + t * 2;
            {
                float sc = irow[lq0];
                int q = q0 + lq0;
                *(float2*)&g_C[((size_t)(b * LL + q)) * DM + hh * 64 + d] =
                    make_float2(c4[i][j][0] * sc, c4[i][j][1] * sc);
            }
            {
                float sc = irow[lq0 + 8];
                int q = q0 + lq0 + 8;
                *(float2*)&g_C[((size_t)(b * LL + q)) * DM + hh * 64 + d] =
                    make_float2(c4[i][j][2] * sc, c4[i][j][3] * sc);
            }
        }
    }
}

// =====================================================================
// Head-mean of attention
// =====================================================================
__global__ void mean_kernel(float* __restrict__ outmean)
{
    size_t idx4 = (size_t)blockIdx.x * 256 + threadIdx.x;
    int k4 = (int)(idx4 & (LL / 4 - 1)) * 4;
    size_t bq = idx4 / (LL / 4);
    int q = (int)(bq & (LL - 1));
    int b = (int)(bq >> 11);
    float ax = 0, ay = 0, az = 0, aw = 0;
    #pragma unroll
    for (int h = 0; h < NH; h++) {
        int bh = b * NH + h;
        float cc = g_c[(size_t)bh * LL + q];
        float4 v = __ldcs((const float4*)&g_P[((size_t)bh * LL + q) * LL + k4]);
        ax += __expf(v.x - cc); ay += __expf(v.y - cc);
        az += __expf(v.z - cc); aw += __expf(v.w - cc);
    }
    const float inv = 1.0f / NH;
    *(float4*)&outmean[bq * LL + k4] = make_float4(ax*inv, ay*inv, az*inv, aw*inv);
}

// =====================================================================
// Output projection (FFMA2, 128x128 tile, 8x8/thread)  [unchanged from R5]
// =====================================================================
__global__ __launch_bounds__(256) void out_gemm(const float* __restrict__ Wo,
                                                const float* __restrict__ bo,
                                                float* __restrict__ out)
{
    const int m0 = blockIdx.y * 128;
    const int n0 = blockIdx.x * 128;
    __shared__ float As[16][132];
    __shared__ float Bs[16][132];

    const int tid = threadIdx.x;
    const int tx = tid & 15, ty = tid >> 4;
    const int arow = tid >> 1, acol = (tid & 1) * 8;
    const int brow = tid >> 4, bcol = (tid & 15) * 8;

    ull accp[8][4] = {};

    for (int kk = 0; kk < DM; kk += 16) {
        if (kk) __syncthreads();
        {
            const float* ap = &g_C[(size_t)(m0 + arow) * DM + kk + acol];
            float4 a0 = *(const float4*)(ap);
            float4 a1 = *(const float4*)(ap + 4);
            As[acol + 0][arow] = a0.x; As[acol + 1][arow] = a0.y;
            As[acol + 2][arow] = a0.z; As[acol + 3][arow] = a0.w;
            As[acol + 4][arow] = a1.x; As[acol + 5][arow] = a1.y;
            As[acol + 6][arow] = a1.z; As[acol + 7][arow] = a1.w;
        }
        {
            const float* bp = &Wo[(size_t)(kk + brow) * DM + n0 + bcol];
            *(float4*)&Bs[brow][bcol]     = *(const float4*)(bp);
            *(float4*)&Bs[brow][bcol + 4] = *(const float4*)(bp + 4);
        }
        __syncthreads();
        #pragma unroll
        for (int k = 0; k < 16; k++) {
            float4 a0 = *(const float4*)&As[k][ty * 4];
            float4 a1 = *(const float4*)&As[k][64 + ty * 4];
            longlong2 bq0 = *(const longlong2*)&Bs[k][tx * 4];
            longlong2 bq1 = *(const longlong2*)&Bs[k][64 + tx * 4];
            ull bb[4] = {(ull)bq0.x, (ull)bq0.y, (ull)bq1.x, (ull)bq1.y};
            ull ad[8] = {dup2(a0.x), dup2(a0.y), dup2(a0.z), dup2(a0.w),
                         dup2(a1.x), dup2(a1.y), dup2(a1.z), dup2(a1.w)};
            #pragma unroll
            for (int i = 0; i < 8; i++)
                #pragma unroll
                for (int jp = 0; jp < 4; jp++)
                    fma2(accp[i][jp], ad[i], bb[jp]);
        }
    }

    #pragma unroll
    for (int i = 0; i < 8; i++) {
        int gm = m0 + (i >> 2) * 64 + ty * 4 + (i & 3);
        #pragma unroll
        for (int gj = 0; gj < 2; gj++) {
            int gn = n0 + gj * 64 + tx * 4;
            float2 p0 = up2(accp[i][gj * 2 + 0]);
            float2 p1 = up2(accp[i][gj * 2 + 1]);
            float4 v = make_float4(p0.x + bo[gn+0], p0.y + bo[gn+1],
                                   p1.x + bo[gn+2], p1.y + bo[gn+3]);
            *(float4*)&out[(size_t)gm * DM + gn] = v;
        }
    }
}

// ---------------- launch ----------------
extern "C" void kernel_launch(void* const* d_in, const int* in_sizes, int n_in,
                              void* d_out, int out_size)
{
    const float* x     = (const float*)d_in[0];
    const float* delta = (const float*)d_in[1];
    const float* Wq    = (const float*)d_in[2];
    const float* bq    = (const float*)d_in[3];
    const float* Wk    = (const float*)d_in[4];
    const float* bk    = (const float*)d_in[5];
    const float* Wv    = (const float*)d_in[6];
    const float* bv    = (const float*)d_in[7];
    const float* Wo    = (const float*)d_in[8];
    const float* bo    = (const float*)d_in[9];
    float* out = (float*)d_out;
    float* outmean = out + (size_t)BB * LL * DM;

    const int SC_SMEM  = (128*68*2 + 128 + 1024) * 4;     // ~74 KB
    const int CTX_SMEM = (128*68 + 64*68 + 256) * 4;      // ~53 KB

    cudaFuncSetAttribute(scores_kernel, cudaFuncAttributeMaxDynamicSharedMemorySize, SC_SMEM);
    cudaFuncSetAttribute(context_kernel, cudaFuncAttributeMaxDynamicSharedMemorySize, CTX_SMEM);

    rb_kernel<<<(BB * LL + 255) / 256, 256>>>(delta);
    qkv_gemm<<<dim3(DM / 128, (BB * LL) / 128, 3), 256>>>(x, delta, Wq, bq, Wk, bk, Wv, bv);
    scores_kernel<<<dim3(LL / 128, BH), 256, SC_SMEM>>>();
    context_kernel<<<dim3(LL / 128, BH), 256, CTX_SMEM>>>();
    mean_kernel<<<(unsigned)((size_t)BB * LL * LL / 4 / 256), 256>>>(outmean);
    out_gemm<<<dim3(DM / 128, (BB * LL) / 128), 256>>>(Wo, bo, out);
}

// round 11
// speedup vs baseline: 1.4463x; 1.2338x over previous
#include <cuda_runtime.h>
#include <math.h>

#define BB 2
#define LL 2048
#define DM 1024
#define NH 16
#define DK 64
#define BH (BB*NH)

typedef unsigned long long ull;

// ---------------- packed f32x2 helpers (FFMA2 path) ----------------
__device__ __forceinline__ ull pk2(float x, float y) {
    ull r; asm("mov.b64 %0,{%1,%2};" : "=l"(r) : "f"(x), "f"(y)); return r;
}
__device__ __forceinline__ ull dup2(float x) { return pk2(x, x); }
__device__ __forceinline__ void fma2(ull& d, ull a, ull b) {
    asm("fma.rn.f32x2 %0,%1,%2,%0;" : "+l"(d) : "l"(a), "l"(b));
}
__device__ __forceinline__ float2 up2(ull v) {
    float2 r; asm("mov.b64 {%0,%1},%2;" : "=f"(r.x), "=f"(r.y) : "l"(v)); return r;
}

// ---------------- tf32 MMA helpers ----------------
__device__ __forceinline__ unsigned f2tf(float f) {
    unsigned u; asm("cvt.rna.tf32.f32 %0, %1;" : "=r"(u) : "f"(f)); return u;
}
__device__ __forceinline__ void mma8(float* c, const unsigned* a, const unsigned* b) {
    asm volatile("mma.sync.aligned.m16n8k8.row.col.f32.tf32.tf32.f32 "
        "{%0,%1,%2,%3}, {%4,%5,%6,%7}, {%8,%9}, {%0,%1,%2,%3};"
        : "+f"(c[0]), "+f"(c[1]), "+f"(c[2]), "+f"(c[3])
        : "r"(a[0]), "r"(a[1]), "r"(a[2]), "r"(a[3]), "r"(b[0]), "r"(b[1]));
}

// ---------------- scratch ----------------
__device__ float g_Q[(size_t)BB*NH*LL*DK];
__device__ float g_K[(size_t)BB*NH*LL*DK];
__device__ float g_V[(size_t)BB*NH*LL*DK];
__device__ float g_C[(size_t)BB*LL*DM];
__device__ float g_P[(size_t)BB*NH*LL*LL];
__device__ float g_m[(size_t)BB*NH*LL];
__device__ float g_s[(size_t)BB*NH*LL];
__device__ float g_c[(size_t)BB*NH*LL];
__device__ float g_rb[(size_t)BB*LL];

// ---------------- rel-bias precompute ----------------
__global__ void rb_kernel(const float* __restrict__ delta)
{
    int i = blockIdx.x * 256 + threadIdx.x;
    if (i < BB*LL) g_rb[i] = logf(delta[i] + 1e-6f);
}

// =====================================================================
// QKV projection (FFMA2, 128x128 tile, 8x8/thread)  [proven R5]
// =====================================================================
__global__ __launch_bounds__(256) void qkv_gemm(
    const float* __restrict__ x, const float* __restrict__ delta,
    const float* __restrict__ Wq, const float* __restrict__ bq,
    const float* __restrict__ Wk, const float* __restrict__ bk,
    const float* __restrict__ Wv, const float* __restrict__ bv)
{
    const int which = blockIdx.z;
    const float* W    = (which == 0) ? Wq : (which == 1) ? Wk : Wv;
    const float* bias = (which == 0) ? bq : (which == 1) ? bk : bv;
    float* O          = (which == 0) ? g_Q : (which == 1) ? g_K : g_V;

    const int m0 = blockIdx.y * 128;
    const int n0 = blockIdx.x * 128;
    __shared__ float As[16][132];
    __shared__ float Bs[16][132];

    const int tid = threadIdx.x;
    const int tx = tid & 15, ty = tid >> 4;

    const int arow = tid >> 1, acol = (tid & 1) * 8;
    const int brow = tid >> 4, bcol = (tid & 15) * 8;
    const float ascale = (which == 2) ? delta[m0 + arow] : 1.0f;

    ull accp[8][4] = {};

    for (int kk = 0; kk < DM; kk += 16) {
        if (kk) __syncthreads();
        {
            const float* ap = &x[(size_t)(m0 + arow) * DM + kk + acol];
            float4 a0 = *(const float4*)(ap);
            float4 a1 = *(const float4*)(ap + 4);
            As[acol + 0][arow] = a0.x * ascale; As[acol + 1][arow] = a0.y * ascale;
            As[acol + 2][arow] = a0.z * ascale; As[acol + 3][arow] = a0.w * ascale;
            As[acol + 4][arow] = a1.x * ascale; As[acol + 5][arow] = a1.y * ascale;
            As[acol + 6][arow] = a1.z * ascale; As[acol + 7][arow] = a1.w * ascale;
        }
        {
            const float* bp = &W[(size_t)(kk + brow) * DM + n0 + bcol];
            *(float4*)&Bs[brow][bcol]     = *(const float4*)(bp);
            *(float4*)&Bs[brow][bcol + 4] = *(const float4*)(bp + 4);
        }
        __syncthreads();
        #pragma unroll
        for (int k = 0; k < 16; k++) {
            float4 a0 = *(const float4*)&As[k][ty * 4];
            float4 a1 = *(const float4*)&As[k][64 + ty * 4];
            longlong2 bq0 = *(const longlong2*)&Bs[k][tx * 4];
            longlong2 bq1 = *(const longlong2*)&Bs[k][64 + tx * 4];
            ull bb[4] = {(ull)bq0.x, (ull)bq0.y, (ull)bq1.x, (ull)bq1.y};
            ull ad[8] = {dup2(a0.x), dup2(a0.y), dup2(a0.z), dup2(a0.w),
                         dup2(a1.x), dup2(a1.y), dup2(a1.z), dup2(a1.w)};
            #pragma unroll
            for (int i = 0; i < 8; i++)
                #pragma unroll
                for (int jp = 0; jp < 4; jp++)
                    fma2(accp[i][jp], ad[i], bb[jp]);
        }
    }

    #pragma unroll
    for (int i = 0; i < 8; i++) {
        int gm = m0 + (i >> 2) * 64 + ty * 4 + (i & 3);
        int b = gm >> 11, l = gm & (LL - 1);
        #pragma unroll
        for (int gj = 0; gj < 2; gj++) {
            int gn = n0 + gj * 64 + tx * 4;
            int h = gn >> 6, d = gn & 63;
            float2 p0 = up2(accp[i][gj * 2 + 0]);
            float2 p1 = up2(accp[i][gj * 2 + 1]);
            float4 v = make_float4(p0.x + bias[gn+0], p0.y + bias[gn+1],
                                   p1.x + bias[gn+2], p1.y + bias[gn+3]);
            *(float4*)&O[(((size_t)(b * NH + h)) * LL + l) * DK + d] = v;
        }
    }
}

// =====================================================================
// Scores v3: Q fragments in registers, K in plain-layout smem tile,
// column-permuted fragments (t->2t, t+4->2t+1). Warp = 16q x all keys.
// =====================================================================
__global__ __launch_bounds__(256, 2) void scores_kernel()
{
    __shared__ unsigned Ks[64][72];   // [key][d] tf32
    __shared__ float rbs[64];

    const int bh = blockIdx.y, b = bh >> 4;
    const int q0 = blockIdx.x * 128;
    const int tid = threadIdx.x, lane = tid & 31, warp = tid >> 5;
    const int g = lane >> 2, t = lane & 3;

    const int row0 = q0 + warp * 16 + g;     // first q row of this thread
    const int row1 = row0 + 8;

    // Q fragments (loop invariant): 8 d-groups x 4 regs
    unsigned qa[8][4];
    {
        const float* q0p = &g_Q[((size_t)bh * LL + row0) * DK + 2 * t];
        const float* q1p = q0p + 8 * DK;
        #pragma unroll
        for (int j = 0; j < 8; j++) {
            float2 lo = *(const float2*)(q0p + 8 * j);
            float2 hi = *(const float2*)(q1p + 8 * j);
            qa[j][0] = f2tf(lo.x); qa[j][1] = f2tf(hi.x);
            qa[j][2] = f2tf(lo.y); qa[j][3] = f2tf(hi.y);
        }
    }

    float mr0 = -1e30f, sr0 = 0.0f, mr1 = -1e30f, sr1 = 0.0f;
    const float qr0 = (float)row0, qr1 = (float)row1;
    float* Prow0 = &g_P[((size_t)bh * LL + row0) * LL];
    float* Prow1 = &g_P[((size_t)bh * LL + row1) * LL];

    for (int kt = 0; kt < LL / 64; kt++) {
        __syncthreads();
        {   // fill K tile 64 keys x 64 d (plain layout, STS.128)
            int krow = tid >> 2, dseg = (tid & 3) * 16;
            const float* kp = &g_K[((size_t)bh * LL + kt * 64 + krow) * DK + dseg];
            #pragma unroll
            for (int c = 0; c < 4; c++) {
                float4 v = *(const float4*)(kp + c * 4);
                unsigned u[4] = {f2tf(v.x), f2tf(v.y), f2tf(v.z), f2tf(v.w)};
                *(uint4*)&Ks[krow][dseg + 4 * c] = *(uint4*)u;
            }
            if (tid < 64) rbs[tid] = g_rb[(size_t)b * LL + kt * 64 + tid];
        }
        __syncthreads();

        float c4[8][4] = {};   // 8 key-tiles of 8
        #pragma unroll
        for (int j = 0; j < 8; j++) {
            #pragma unroll
            for (int jn = 0; jn < 8; jn++) {
                uint2 bb = *(const uint2*)&Ks[jn * 8 + g][8 * j + 2 * t];
                unsigned bfr[2] = {bb.x, bb.y};
                mma8(c4[jn], qa[j], bfr);
            }
        }

        // rel-bias values for this thread's key columns (shared by both rows)
        float rbv[16];
        #pragma unroll
        for (int jn = 0; jn < 8; jn++) {
            rbv[2*jn]   = rbs[jn * 8 + 2 * t];
            rbv[2*jn+1] = rbs[jn * 8 + 2 * t + 1];
        }

        // ---- row 0 ----
        {
            float sv[16]; float vmax = -1e30f;
            #pragma unroll
            for (int jn = 0; jn < 8; jn++) {
                int kg = kt * 64 + jn * 8 + 2 * t;
                float v0 = c4[jn][0] * 0.125f - 0.1f * fabsf(qr0 - (float)kg)       + rbv[2*jn];
                float v1 = c4[jn][1] * 0.125f - 0.1f * fabsf(qr0 - (float)(kg + 1)) + rbv[2*jn+1];
                sv[2*jn] = v0; sv[2*jn+1] = v1;
                vmax = fmaxf(vmax, fmaxf(v0, v1));
                __stcs((float2*)&Prow0[kg], make_float2(v0, v1));
            }
            vmax = fmaxf(vmax, __shfl_xor_sync(0xffffffffu, vmax, 1));
            vmax = fmaxf(vmax, __shfl_xor_sync(0xffffffffu, vmax, 2));
            float newm = fmaxf(mr0, vmax);
            float se = 0.0f;
            #pragma unroll
            for (int u = 0; u < 16; u++) se += __expf(sv[u] - newm);
            se += __shfl_xor_sync(0xffffffffu, se, 1);
            se += __shfl_xor_sync(0xffffffffu, se, 2);
            sr0 = sr0 * __expf(mr0 - newm) + se;
            mr0 = newm;
        }
        // ---- row 1 ----
        {
            float sv[16]; float vmax = -1e30f;
            #pragma unroll
            for (int jn = 0; jn < 8; jn++) {
                int kg = kt * 64 + jn * 8 + 2 * t;
                float v0 = c4[jn][2] * 0.125f - 0.1f * fabsf(qr1 - (float)kg)       + rbv[2*jn];
                float v1 = c4[jn][3] * 0.125f - 0.1f * fabsf(qr1 - (float)(kg + 1)) + rbv[2*jn+1];
                sv[2*jn] = v0; sv[2*jn+1] = v1;
                vmax = fmaxf(vmax, fmaxf(v0, v1));
                __stcs((float2*)&Prow1[kg], make_float2(v0, v1));
            }
            vmax = fmaxf(vmax, __shfl_xor_sync(0xffffffffu, vmax, 1));
            vmax = fmaxf(vmax, __shfl_xor_sync(0xffffffffu, vmax, 2));
            float newm = fmaxf(mr1, vmax);
            float se = 0.0f;
            #pragma unroll
            for (int u = 0; u < 16; u++) se += __expf(sv[u] - newm);
            se += __shfl_xor_sync(0xffffffffu, se, 1);
            se += __shfl_xor_sync(0xffffffffu, se, 2);
            sr1 = sr1 * __expf(mr1 - newm) + se;
            mr1 = newm;
        }
    }

    if (t == 0) {
        size_t r0 = (size_t)bh * LL + row0;
        size_t r1 = (size_t)bh * LL + row1;
        g_m[r0] = mr0; g_s[r0] = sr0; g_c[r0] = mr0 + __logf(sr0);
        g_m[r1] = mr1; g_s[r1] = sr1; g_c[r1] = mr1 + __logf(sr1);
    }
}

// =====================================================================
// Context v3: P streamed gmem->reg fragments (exp in regs), V in plain
// smem tile. Warp = 16q x 64d. Each P element read exactly once.
// =====================================================================
__global__ __launch_bounds__(256) void context_kernel()
{
    __shared__ unsigned Vs[64][72];   // [d][key] tf32

    const int bh = blockIdx.y, b = bh >> 4, hh = bh & 15;
    const int q0 = blockIdx.x * 128;
    const int tid = threadIdx.x, lane = tid & 31, warp = tid >> 5;
    const int g = lane >> 2, t = lane & 3;

    const int row0 = q0 + warp * 16 + g;
    const int row1 = row0 + 8;
    const float m0 = g_m[(size_t)bh * LL + row0];
    const float m1 = g_m[(size_t)bh * LL + row1];
    const float is0 = 1.0f / g_s[(size_t)bh * LL + row0];
    const float is1 = 1.0f / g_s[(size_t)bh * LL + row1];

    const float* Pr0 = &g_P[((size_t)bh * LL + row0) * LL + 2 * t];
    const float* Pr1 = Pr0 + 8 * LL;

    const int vd = tid & 63, vseg = tid >> 6;

    float c4[8][4] = {};   // 8 d-tiles of 8

    for (int kc = 0; kc < LL; kc += 64) {
        __syncthreads();
        {   // V tile: 64 keys x 64 d -> Vs[d][key] (coalesced gather)
            const float* vb = &g_V[((size_t)bh * LL + kc + vseg * 16) * DK + vd];
            #pragma unroll
            for (int c = 0; c < 4; c++) {
                unsigned u[4];
                #pragma unroll
                for (int i2 = 0; i2 < 4; i2++)
                    u[i2] = f2tf(vb[(size_t)(c * 4 + i2) * DK]);
                *(uint4*)&Vs[vd][vseg * 16 + 4 * c] = *(uint4*)u;
            }
        }
        __syncthreads();

        #pragma unroll
        for (int j = 0; j < 8; j++) {
            float2 lo = __ldcs((const float2*)(Pr0 + kc + 8 * j));
            float2 hi = __ldcs((const float2*)(Pr1 + kc + 8 * j));
            unsigned a[4];
            a[0] = f2tf(__expf(lo.x - m0));
            a[1] = f2tf(__expf(hi.x - m1));
            a[2] = f2tf(__expf(lo.y - m0));
            a[3] = f2tf(__expf(hi.y - m1));
            #pragma unroll
            for (int jn = 0; jn < 8; jn++) {
                uint2 bb = *(const uint2*)&Vs[jn * 8 + g][8 * j + 2 * t];
                unsigned bfr[2] = {bb.x, bb.y};
                mma8(c4[jn], a, bfr);
            }
        }
    }

    float* Cr0 = &g_C[((size_t)(b * LL + row0)) * DM + hh * 64 + 2 * t];
    float* Cr1 = &g_C[((size_t)(b * LL + row1)) * DM + hh * 64 + 2 * t];
    #pragma unroll
    for (int jn = 0; jn < 8; jn++) {
        *(float2*)(Cr0 + jn * 8) = make_float2(c4[jn][0] * is0, c4[jn][1] * is0);
        *(float2*)(Cr1 + jn * 8) = make_float2(c4[jn][2] * is1, c4[jn][3] * is1);
    }
}

// =====================================================================
// Head-mean of attention
// =====================================================================
__global__ void mean_kernel(float* __restrict__ outmean)
{
    size_t idx4 = (size_t)blockIdx.x * 256 + threadIdx.x;
    int k4 = (int)(idx4 & (LL / 4 - 1)) * 4;
    size_t bq = idx4 / (LL / 4);
    int q = (int)(bq & (LL - 1));
    int b = (int)(bq >> 11);
    float ax = 0, ay = 0, az = 0, aw = 0;
    #pragma unroll
    for (int h = 0; h < NH; h++) {
        int bh = b * NH + h;
        float cc = g_c[(size_t)bh * LL + q];
        float4 v = __ldcs((const float4*)&g_P[((size_t)bh * LL + q) * LL + k4]);
        ax += __expf(v.x - cc); ay += __expf(v.y - cc);
        az += __expf(v.z - cc); aw += __expf(v.w - cc);
    }
    const float inv = 1.0f / NH;
    *(float4*)&outmean[bq * LL + k4] = make_float4(ax*inv, ay*inv, az*inv, aw*inv);
}

// =====================================================================
// Output projection (FFMA2, 128x128 tile, 8x8/thread)  [proven R5]
// =====================================================================
__global__ __launch_bounds__(256) void out_gemm(const float* __restrict__ Wo,
                                                const float* __restrict__ bo,
                                                float* __restrict__ out)
{
    const int m0 = blockIdx.y * 128;
    const int n0 = blockIdx.x * 128;
    __shared__ float As[16][132];
    __shared__ float Bs[16][132];

    const int tid = threadIdx.x;
    const int tx = tid & 15, ty = tid >> 4;
    const int arow = tid >> 1, acol = (tid & 1) * 8;
    const int brow = tid >> 4, bcol = (tid & 15) * 8;

    ull accp[8][4] = {};

    for (int kk = 0; kk < DM; kk += 16) {
        if (kk) __syncthreads();
        {
            const float* ap = &g_C[(size_t)(m0 + arow) * DM + kk + acol];
            float4 a0 = *(const float4*)(ap);
            float4 a1 = *(const float4*)(ap + 4);
            As[acol + 0][arow] = a0.x; As[acol + 1][arow] = a0.y;
            As[acol + 2][arow] = a0.z; As[acol + 3][arow] = a0.w;
            As[acol + 4][arow] = a1.x; As[acol + 5][arow] = a1.y;
            As[acol + 6][arow] = a1.z; As[acol + 7][arow] = a1.w;
        }
        {
            const float* bp = &Wo[(size_t)(kk + brow) * DM + n0 + bcol];
            *(float4*)&Bs[brow][bcol]     = *(const float4*)(bp);
            *(float4*)&Bs[brow][bcol + 4] = *(const float4*)(bp + 4);
        }
        __syncthreads();
        #pragma unroll
        for (int k = 0; k < 16; k++) {
            float4 a0 = *(const float4*)&As[k][ty * 4];
            float4 a1 = *(const float4*)&As[k][64 + ty * 4];
            longlong2 bq0 = *(const longlong2*)&Bs[k][tx * 4];
            longlong2 bq1 = *(const longlong2*)&Bs[k][64 + tx * 4];
            ull bb[4] = {(ull)bq0.x, (ull)bq0.y, (ull)bq1.x, (ull)bq1.y};
            ull ad[8] = {dup2(a0.x), dup2(a0.y), dup2(a0.z), dup2(a0.w),
                         dup2(a1.x), dup2(a1.y), dup2(a1.z), dup2(a1.w)};
            #pragma unroll
            for (int i = 0; i < 8; i++)
                #pragma unroll
                for (int jp = 0; jp < 4; jp++)
                    fma2(accp[i][jp], ad[i], bb[jp]);
        }
    }

    #pragma unroll
    for (int i = 0; i < 8; i++) {
        int gm = m0 + (i >> 2) * 64 + ty * 4 + (i & 3);
        #pragma unroll
        for (int gj = 0; gj < 2; gj++) {
            int gn = n0 + gj * 64 + tx * 4;
            float2 p0 = up2(accp[i][gj * 2 + 0]);
            float2 p1 = up2(accp[i][gj * 2 + 1]);
            float4 v = make_float4(p0.x + bo[gn+0], p0.y + bo[gn+1],
                                   p1.x + bo[gn+2], p1.y + bo[gn+3]);
            *(float4*)&out[(size_t)gm * DM + gn] = v;
        }
    }
}

// ---------------- launch ----------------
extern "C" void kernel_launch(void* const* d_in, const int* in_sizes, int n_in,
                              void* d_out, int out_size)
{
    const float* x     = (const float*)d_in[0];
    const float* delta = (const float*)d_in[1];
    const float* Wq    = (const float*)d_in[2];
    const float* bq    = (const float*)d_in[3];
    const float* Wk    = (const float*)d_in[4];
    const float* bk    = (const float*)d_in[5];
    const float* Wv    = (const float*)d_in[6];
    const float* bv    = (const float*)d_in[7];
    const float* Wo    = (const float*)d_in[8];
    const float* bo    = (const float*)d_in[9];
    float* out = (float*)d_out;
    float* outmean = out + (size_t)BB * LL * DM;

    rb_kernel<<<(BB * LL + 255) / 256, 256>>>(delta);
    qkv_gemm<<<dim3(DM / 128, (BB * LL) / 128, 3), 256>>>(x, delta, Wq, bq, Wk, bk, Wv, bv);
    scores_kernel<<<dim3(LL / 128, BH), 256>>>();
    context_kernel<<<dim3(LL / 128, BH), 256>>>();
    mean_kernel<<<(unsigned)((size_t)BB * LL * LL / 4 / 256), 256>>>(outmean);
    out_gemm<<<dim3(DM / 128, (BB * LL) / 128), 256>>>(Wo, bo, out);
}

// round 12
// speedup vs baseline: 2.0249x; 1.4001x over previous
#include <cuda_runtime.h>
#include <math.h>

#define BB 2
#define LL 2048
#define DM 1024
#define NH 16
#define DK 64
#define BH (BB*NH)

// ---------------- tf32 MMA helpers ----------------
__device__ __forceinline__ unsigned f2tf(float f) {
    unsigned u; asm("cvt.rna.tf32.f32 %0, %1;" : "=r"(u) : "f"(f)); return u;
}
__device__ __forceinline__ void mma8(float* c, const unsigned* a, const unsigned* b) {
    asm volatile("mma.sync.aligned.m16n8k8.row.col.f32.tf32.tf32.f32 "
        "{%0,%1,%2,%3}, {%4,%5,%6,%7}, {%8,%9}, {%0,%1,%2,%3};"
        : "+f"(c[0]), "+f"(c[1]), "+f"(c[2]), "+f"(c[3])
        : "r"(a[0]), "r"(a[1]), "r"(a[2]), "r"(a[3]), "r"(b[0]), "r"(b[1]));
}

// ---------------- scratch ----------------
__device__ float g_Q[(size_t)BB*NH*LL*DK];
__device__ float g_K[(size_t)BB*NH*LL*DK];
__device__ float g_V[(size_t)BB*NH*LL*DK];
__device__ float g_C[(size_t)BB*LL*DM];
__device__ float g_P[(size_t)BB*NH*LL*LL];
__device__ float g_m[(size_t)BB*NH*LL];
__device__ float g_s[(size_t)BB*NH*LL];
__device__ float g_c[(size_t)BB*NH*LL];
__device__ float g_rb[(size_t)BB*LL];
__device__ float g_WT[4][(size_t)DM*DM];   // transposed weights [n][k]

// ---------------- rel-bias precompute ----------------
__global__ void rb_kernel(const float* __restrict__ delta)
{
    int i = blockIdx.x * 256 + threadIdx.x;
    if (i < BB*LL) g_rb[i] = logf(delta[i] + 1e-6f);
}

// ---------------- weight transpose (once, 4 matrices) ----------------
__global__ void wt_kernel(const float* __restrict__ Wq, const float* __restrict__ Wk,
                          const float* __restrict__ Wv, const float* __restrict__ Wo)
{
    __shared__ float t[32][33];
    const int which = blockIdx.z;
    const float* W = (which == 0) ? Wq : (which == 1) ? Wk : (which == 2) ? Wv : Wo;
    const int x0 = blockIdx.x * 32, y0 = blockIdx.y * 32;
    const int tx = threadIdx.x, ty = threadIdx.y;
    #pragma unroll
    for (int i = 0; i < 32; i += 8)
        t[ty + i][tx] = W[(size_t)(y0 + ty + i) * DM + x0 + tx];
    __syncthreads();
    float* WT = g_WT[which];
    #pragma unroll
    for (int i = 0; i < 32; i += 8)
        WT[(size_t)(x0 + ty + i) * DM + y0 + tx] = t[tx][ty + i];
}

// =====================================================================
// QKV projection: single tf32 MMA, scores-style data path.
// Block: 128m x 64n, 8 warps of 16m x 64n. K chunks of 64.
// =====================================================================
__global__ __launch_bounds__(256) void qkv_tf32(
    const float* __restrict__ x, const float* __restrict__ delta,
    const float* __restrict__ bq, const float* __restrict__ bk,
    const float* __restrict__ bv)
{
    __shared__ unsigned Ws[64][72];   // [n][k] tf32

    const int which = blockIdx.z;
    const float* bias = (which == 0) ? bq : (which == 1) ? bk : bv;
    float* O          = (which == 0) ? g_Q : (which == 1) ? g_K : g_V;
    const float* WT   = g_WT[which];

    const int n0 = blockIdx.x * 64, m0 = blockIdx.y * 128;
    const int tid = threadIdx.x, lane = tid & 31, warp = tid >> 5;
    const int g = lane >> 2, t = lane & 3;

    const int row0 = m0 + warp * 16 + g, row1 = row0 + 8;
    float s0 = 1.0f, s1 = 1.0f;
    if (which == 2) { s0 = delta[row0]; s1 = delta[row1]; }

    const float* a0p = x + (size_t)row0 * DM + 2 * t;
    const float* a1p = x + (size_t)row1 * DM + 2 * t;

    const int wn = tid >> 2, wk = (tid & 3) * 16;
    const float* wfill = WT + (size_t)(n0 + wn) * DM + wk;

    float c4[8][4] = {};

    for (int k0 = 0; k0 < DM; k0 += 64) {
        __syncthreads();
        #pragma unroll
        for (int c = 0; c < 4; c++) {
            float4 v = *(const float4*)(wfill + k0 + c * 4);
            unsigned u[4] = {f2tf(v.x), f2tf(v.y), f2tf(v.z), f2tf(v.w)};
            *(uint4*)&Ws[wn][wk + 4 * c] = *(uint4*)u;
        }
        __syncthreads();
        #pragma unroll
        for (int j = 0; j < 8; j++) {
            float2 lo = *(const float2*)(a0p + k0 + 8 * j);
            float2 hi = *(const float2*)(a1p + k0 + 8 * j);
            unsigned a[4] = {f2tf(lo.x * s0), f2tf(hi.x * s1),
                             f2tf(lo.y * s0), f2tf(hi.y * s1)};
            #pragma unroll
            for (int jn = 0; jn < 8; jn++) {
                uint2 bb = *(const uint2*)&Ws[jn * 8 + g][8 * j + 2 * t];
                unsigned bfr[2] = {bb.x, bb.y};
                mma8(c4[jn], a, bfr);
            }
        }
    }

    const int b0 = row0 >> 11, l0 = row0 & (LL - 1);
    const int b1 = row1 >> 11, l1 = row1 & (LL - 1);
    #pragma unroll
    for (int jn = 0; jn < 8; jn++) {
        int gn = n0 + jn * 8 + 2 * t;
        int h = gn >> 6, d = gn & 63;
        float bsx = bias[gn], bsy = bias[gn + 1];
        *(float2*)&O[(((size_t)(b0 * NH + h)) * LL + l0) * DK + d] =
            make_float2(c4[jn][0] + bsx, c4[jn][1] + bsy);
        *(float2*)&O[(((size_t)(b1 * NH + h)) * LL + l1) * DK + d] =
            make_float2(c4[jn][2] + bsx, c4[jn][3] + bsy);
    }
}

// =====================================================================
// Scores: Q frags in regs, K plain smem tile  [proven R11]
// =====================================================================
__global__ __launch_bounds__(256, 2) void scores_kernel()
{
    __shared__ unsigned Ks[64][72];   // [key][d] tf32
    __shared__ float rbs[64];

    const int bh = blockIdx.y, b = bh >> 4;
    const int q0 = blockIdx.x * 128;
    const int tid = threadIdx.x, lane = tid & 31, warp = tid >> 5;
    const int g = lane >> 2, t = lane & 3;

    const int row0 = q0 + warp * 16 + g;
    const int row1 = row0 + 8;

    unsigned qa[8][4];
    {
        const float* q0p = &g_Q[((size_t)bh * LL + row0) * DK + 2 * t];
        const float* q1p = q0p + 8 * DK;
        #pragma unroll
        for (int j = 0; j < 8; j++) {
            float2 lo = *(const float2*)(q0p + 8 * j);
            float2 hi = *(const float2*)(q1p + 8 * j);
            qa[j][0] = f2tf(lo.x); qa[j][1] = f2tf(hi.x);
            qa[j][2] = f2tf(lo.y); qa[j][3] = f2tf(hi.y);
        }
    }

    float mr0 = -1e30f, sr0 = 0.0f, mr1 = -1e30f, sr1 = 0.0f;
    const float qr0 = (float)row0, qr1 = (float)row1;
    float* Prow0 = &g_P[((size_t)bh * LL + row0) * LL];
    float* Prow1 = &g_P[((size_t)bh * LL + row1) * LL];

    for (int kt = 0; kt < LL / 64; kt++) {
        __syncthreads();
        {
            int krow = tid >> 2, dseg = (tid & 3) * 16;
            const float* kp = &g_K[((size_t)bh * LL + kt * 64 + krow) * DK + dseg];
            #pragma unroll
            for (int c = 0; c < 4; c++) {
                float4 v = *(const float4*)(kp + c * 4);
                unsigned u[4] = {f2tf(v.x), f2tf(v.y), f2tf(v.z), f2tf(v.w)};
                *(uint4*)&Ks[krow][dseg + 4 * c] = *(uint4*)u;
            }
            if (tid < 64) rbs[tid] = g_rb[(size_t)b * LL + kt * 64 + tid];
        }
        __syncthreads();

        float c4[8][4] = {};
        #pragma unroll
        for (int j = 0; j < 8; j++) {
            #pragma unroll
            for (int jn = 0; jn < 8; jn++) {
                uint2 bb = *(const uint2*)&Ks[jn * 8 + g][8 * j + 2 * t];
                unsigned bfr[2] = {bb.x, bb.y};
                mma8(c4[jn], qa[j], bfr);
            }
        }

        float rbv[16];
        #pragma unroll
        for (int jn = 0; jn < 8; jn++) {
            rbv[2*jn]   = rbs[jn * 8 + 2 * t];
            rbv[2*jn+1] = rbs[jn * 8 + 2 * t + 1];
        }

        {
            float sv[16]; float vmax = -1e30f;
            #pragma unroll
            for (int jn = 0; jn < 8; jn++) {
                int kg = kt * 64 + jn * 8 + 2 * t;
                float v0 = c4[jn][0] * 0.125f - 0.1f * fabsf(qr0 - (float)kg)       + rbv[2*jn];
                float v1 = c4[jn][1] * 0.125f - 0.1f * fabsf(qr0 - (float)(kg + 1)) + rbv[2*jn+1];
                sv[2*jn] = v0; sv[2*jn+1] = v1;
                vmax = fmaxf(vmax, fmaxf(v0, v1));
                __stcs((float2*)&Prow0[kg], make_float2(v0, v1));
            }
            vmax = fmaxf(vmax, __shfl_xor_sync(0xffffffffu, vmax, 1));
            vmax = fmaxf(vmax, __shfl_xor_sync(0xffffffffu, vmax, 2));
            float newm = fmaxf(mr0, vmax);
            float se = 0.0f;
            #pragma unroll
            for (int u = 0; u < 16; u++) se += __expf(sv[u] - newm);
            se += __shfl_xor_sync(0xffffffffu, se, 1);
            se += __shfl_xor_sync(0xffffffffu, se, 2);
            sr0 = sr0 * __expf(mr0 - newm) + se;
            mr0 = newm;
        }
        {
            float sv[16]; float vmax = -1e30f;
            #pragma unroll
            for (int jn = 0; jn < 8; jn++) {
                int kg = kt * 64 + jn * 8 + 2 * t;
                float v0 = c4[jn][2] * 0.125f - 0.1f * fabsf(qr1 - (float)kg)       + rbv[2*jn];
                float v1 = c4[jn][3] * 0.125f - 0.1f * fabsf(qr1 - (float)(kg + 1)) + rbv[2*jn+1];
                sv[2*jn] = v0; sv[2*jn+1] = v1;
                vmax = fmaxf(vmax, fmaxf(v0, v1));
                __stcs((float2*)&Prow1[kg], make_float2(v0, v1));
            }
            vmax = fmaxf(vmax, __shfl_xor_sync(0xffffffffu, vmax, 1));
            vmax = fmaxf(vmax, __shfl_xor_sync(0xffffffffu, vmax, 2));
            float newm = fmaxf(mr1, vmax);
            float se = 0.0f;
            #pragma unroll
            for (int u = 0; u < 16; u++) se += __expf(sv[u] - newm);
            se += __shfl_xor_sync(0xffffffffu, se, 1);
            se += __shfl_xor_sync(0xffffffffu, se, 2);
            sr1 = sr1 * __expf(mr1 - newm) + se;
            mr1 = newm;
        }
    }

    if (t == 0) {
        size_t r0 = (size_t)bh * LL + row0;
        size_t r1 = (size_t)bh * LL + row1;
        g_m[r0] = mr0; g_s[r0] = sr0; g_c[r0] = mr0 + __logf(sr0);
        g_m[r1] = mr1; g_s[r1] = sr1; g_c[r1] = mr1 + __logf(sr1);
    }
}

// =====================================================================
// Context: P streamed gmem->reg, V plain smem tile  [proven R11]
// =====================================================================
__global__ __launch_bounds__(256) void context_kernel()
{
    __shared__ unsigned Vs[64][72];   // [d][key] tf32

    const int bh = blockIdx.y, b = bh >> 4, hh = bh & 15;
    const int q0 = blockIdx.x * 128;
    const int tid = threadIdx.x, lane = tid & 31, warp = tid >> 5;
    const int g = lane >> 2, t = lane & 3;

    const int row0 = q0 + warp * 16 + g;
    const int row1 = row0 + 8;
    const float m0 = g_m[(size_t)bh * LL + row0];
    const float m1 = g_m[(size_t)bh * LL + row1];
    const float is0 = 1.0f / g_s[(size_t)bh * LL + row0];
    const float is1 = 1.0f / g_s[(size_t)bh * LL + row1];

    const float* Pr0 = &g_P[((size_t)bh * LL + row0) * LL + 2 * t];
    const float* Pr1 = Pr0 + 8 * LL;

    const int vd = tid & 63, vseg = tid >> 6;

    float c4[8][4] = {};

    for (int kc = 0; kc < LL; kc += 64) {
        __syncthreads();
        {
            const float* vb = &g_V[((size_t)bh * LL + kc + vseg * 16) * DK + vd];
            #pragma unroll
            for (int c = 0; c < 4; c++) {
                unsigned u[4];
                #pragma unroll
                for (int i2 = 0; i2 < 4; i2++)
                    u[i2] = f2tf(vb[(size_t)(c * 4 + i2) * DK]);
                *(uint4*)&Vs[vd][vseg * 16 + 4 * c] = *(uint4*)u;
            }
        }
        __syncthreads();

        #pragma unroll
        for (int j = 0; j < 8; j++) {
            float2 lo = __ldcs((const float2*)(Pr0 + kc + 8 * j));
            float2 hi = __ldcs((const float2*)(Pr1 + kc + 8 * j));
            unsigned a[4];
            a[0] = f2tf(__expf(lo.x - m0));
            a[1] = f2tf(__expf(hi.x - m1));
            a[2] = f2tf(__expf(lo.y - m0));
            a[3] = f2tf(__expf(hi.y - m1));
            #pragma unroll
            for (int jn = 0; jn < 8; jn++) {
                uint2 bb = *(const uint2*)&Vs[jn * 8 + g][8 * j + 2 * t];
                unsigned bfr[2] = {bb.x, bb.y};
                mma8(c4[jn], a, bfr);
            }
        }
    }

    float* Cr0 = &g_C[((size_t)(b * LL + row0)) * DM + hh * 64 + 2 * t];
    float* Cr1 = &g_C[((size_t)(b * LL + row1)) * DM + hh * 64 + 2 * t];
    #pragma unroll
    for (int jn = 0; jn < 8; jn++) {
        *(float2*)(Cr0 + jn * 8) = make_float2(c4[jn][0] * is0, c4[jn][1] * is0);
        *(float2*)(Cr1 + jn * 8) = make_float2(c4[jn][2] * is1, c4[jn][3] * is1);
    }
}

// =====================================================================
// Head-mean of attention
// =====================================================================
__global__ void mean_kernel(float* __restrict__ outmean)
{
    size_t idx4 = (size_t)blockIdx.x * 256 + threadIdx.x;
    int k4 = (int)(idx4 & (LL / 4 - 1)) * 4;
    size_t bq = idx4 / (LL / 4);
    int q = (int)(bq & (LL - 1));
    int b = (int)(bq >> 11);
    float ax = 0, ay = 0, az = 0, aw = 0;
    #pragma unroll
    for (int h = 0; h < NH; h++) {
        int bh = b * NH + h;
        float cc = g_c[(size_t)bh * LL + q];
        float4 v = __ldcs((const float4*)&g_P[((size_t)bh * LL + q) * LL + k4]);
        ax += __expf(v.x - cc); ay += __expf(v.y - cc);
        az += __expf(v.z - cc); aw += __expf(v.w - cc);
    }
    const float inv = 1.0f / NH;
    *(float4*)&outmean[bq * LL + k4] = make_float4(ax*inv, ay*inv, az*inv, aw*inv);
}

// =====================================================================
// Output projection: single tf32 MMA, same structure as qkv_tf32
// =====================================================================
__global__ __launch_bounds__(256) void out_tf32(const float* __restrict__ bo,
                                                float* __restrict__ out)
{
    __shared__ unsigned Ws[64][72];

    const float* WT = g_WT[3];
    const int n0 = blockIdx.x * 64, m0 = blockIdx.y * 128;
    const int tid = threadIdx.x, lane = tid & 31, warp = tid >> 5;
    const int g = lane >> 2, t = lane & 3;

    const int row0 = m0 + warp * 16 + g, row1 = row0 + 8;
    const float* a0p = g_C + (size_t)row0 * DM + 2 * t;
    const float* a1p = g_C + (size_t)row1 * DM + 2 * t;

    const int wn = tid >> 2, wk = (tid & 3) * 16;
    const float* wfill = WT + (size_t)(n0 + wn) * DM + wk;

    float c4[8][4] = {};

    for (int k0 = 0; k0 < DM; k0 += 64) {
        __syncthreads();
        #pragma unroll
        for (int c = 0; c < 4; c++) {
            float4 v = *(const float4*)(wfill + k0 + c * 4);
            unsigned u[4] = {f2tf(v.x), f2tf(v.y), f2tf(v.z), f2tf(v.w)};
            *(uint4*)&Ws[wn][wk + 4 * c] = *(uint4*)u;
        }
        __syncthreads();
        #pragma unroll
        for (int j = 0; j < 8; j++) {
            float2 lo = *(const float2*)(a0p + k0 + 8 * j);
            float2 hi = *(const float2*)(a1p + k0 + 8 * j);
            unsigned a[4] = {f2tf(lo.x), f2tf(hi.x), f2tf(lo.y), f2tf(hi.y)};
            #pragma unroll
            for (int jn = 0; jn < 8; jn++) {
                uint2 bb = *(const uint2*)&Ws[jn * 8 + g][8 * j + 2 * t];
                unsigned bfr[2] = {bb.x, bb.y};
                mma8(c4[jn], a, bfr);
            }
        }
    }

    #pragma unroll
    for (int jn = 0; jn < 8; jn++) {
        int gn = n0 + jn * 8 + 2 * t;
        float bsx = bo[gn], bsy = bo[gn + 1];
        *(float2*)&out[(size_t)row0 * DM + gn] = make_float2(c4[jn][0] + bsx, c4[jn][1] + bsy);
        *(float2*)&out[(size_t)row1 * DM + gn] = make_float2(c4[jn][2] + bsx, c4[jn][3] + bsy);
    }
}

// ---------------- launch ----------------
extern "C" void kernel_launch(void* const* d_in, const int* in_sizes, int n_in,
                              void* d_out, int out_size)
{
    const float* x     = (const float*)d_in[0];
    const float* delta = (const float*)d_in[1];
    const float* Wq    = (const float*)d_in[2];
    const float* bq    = (const float*)d_in[3];
    const float* Wk    = (const float*)d_in[4];
    const float* bk    = (const float*)d_in[5];
    const float* Wv    = (const float*)d_in[6];
    const float* bv    = (const float*)d_in[7];
    const float* Wo    = (const float*)d_in[8];
    const float* bo    = (const float*)d_in[9];
    float* out = (float*)d_out;
    float* outmean = out + (size_t)BB * LL * DM;

    rb_kernel<<<(BB * LL + 255) / 256, 256>>>(delta);
    wt_kernel<<<dim3(32, 32, 4), dim3(32, 8)>>>(Wq, Wk, Wv, Wo);
    qkv_tf32<<<dim3(DM / 64, (BB * LL) / 128, 3), 256>>>(x, delta, bq, bk, bv);
    scores_kernel<<<dim3(LL / 128, BH), 256>>>();
    context_kernel<<<dim3(LL / 128, BH), 256>>>();
    mean_kernel<<<(unsigned)((size_t)BB * LL * LL / 4 / 256), 256>>>(outmean);
    out_tf32<<<dim3(DM / 64, (BB * LL) / 128), 256>>>(bo, out);
}